// round 3
// baseline (speedup 1.0000x reference)
#include <cuda_runtime.h>

#define T_BINS 151
#define TILE   64
#define PADW   132          // 128 + 4 floats pad: float4-aligned, bank-offset 4/row
#define MAXB   600

// Per-block partial results: [0..150] pos hist, [151..301] neg hist, [302] pos count.
// Each block fully overwrites its own row -> no zero-init kernel needed.
__device__ float g_part[MAXB][2 * T_BINS + 4];

__global__ __launch_bounds__(256) void hist_pairs_kernel(
    const float* __restrict__ feats, const int* __restrict__ cls,
    int N, int NT)
{
    extern __shared__ float sm[];
    float* As   = sm;                         // TILE x PADW
    float* Bs   = As + TILE * PADW;           // TILE x PADW
    float* hist = Bs + TILE * PADW;           // 2 * T_BINS
    int*   clsA = (int*)(hist + 2 * T_BINS);  // TILE
    int*   clsB = clsA + TILE;                // TILE
    int*   sPos = clsB + TILE;                // 1

    const int tid = threadIdx.x;

    // Decode linear block id -> upper-triangular tile (bi, bj), bi <= bj.
    int k = blockIdx.x, bi = 0;
    while (k >= NT - bi) { k -= NT - bi; ++bi; }
    const int bj = bi + k;

    for (int i = tid; i < 2 * T_BINS; i += 256) hist[i] = 0.0f;
    if (tid == 0) *sPos = 0;
    if (tid < TILE) {
        int gi = bi * TILE + tid;
        clsA[tid] = (gi < N) ? cls[gi] : -1;
        int gj = bj * TILE + tid;
        clsB[tid] = (gj < N) ? cls[gj] : -2;
    }

    // Load both feature tiles (64 rows x 128 floats each) as float4, coalesced.
    const float4* f4 = (const float4*)feats;
    for (int idx = tid; idx < TILE * 32; idx += 256) {
        int r = idx >> 5, c = idx & 31;
        int gi = bi * TILE + r;
        float4 va = (gi < N) ? f4[gi * 32 + c] : make_float4(0.f, 0.f, 0.f, 0.f);
        *(float4*)(As + r * PADW + c * 4) = va;
        int gj = bj * TILE + r;
        float4 vb = (gj < N) ? f4[gj * 32 + c] : make_float4(0.f, 0.f, 0.f, 0.f);
        *(float4*)(Bs + r * PADW + c * 4) = vb;
    }
    __syncthreads();

    const int tr = tid >> 4;   // 0..15
    const int tc = tid & 15;   // 0..15

    // 4x4 register micro-tile: rows tr + 16u, cols tc + 16v.
    float acc[4][4];
#pragma unroll
    for (int u = 0; u < 4; ++u)
#pragma unroll
        for (int v = 0; v < 4; ++v) acc[u][v] = 0.0f;

    for (int kk = 0; kk < 128; kk += 4) {
        float4 a[4], b[4];
#pragma unroll
        for (int u = 0; u < 4; ++u)
            a[u] = *(const float4*)(As + (tr + 16 * u) * PADW + kk);
#pragma unroll
        for (int v = 0; v < 4; ++v)
            b[v] = *(const float4*)(Bs + (tc + 16 * v) * PADW + kk);
#pragma unroll
        for (int u = 0; u < 4; ++u)
#pragma unroll
            for (int v = 0; v < 4; ++v)
                acc[u][v] += a[u].x * b[v].x + a[u].y * b[v].y
                           + a[u].z * b[v].z + a[u].w * b[v].w;
    }

    // ---- Binning: bit-exact replication of the reference's fp32 semantics ----
    // Reference (all fp32, NO FMA contraction — XLA emits mul-then-add):
    //   delta = floor((s+1)/step)*step - 1
    //   indsb (bin q):    delta == -1 + q*step        -> ALWAYS true bitwise
    //   indsa (bin q+1):  delta == (-1+(q+1)*step) - step
    //                      -> different rounding path, usually FALSE; wa dropped.
    // Every op below uses explicit _rn intrinsics so nvcc CANNOT contract to
    // FMA (FMA single-rounding changed the equality outcome -> R2 failure).
    const float step = (float)(2.0 / 150.0);
    int localPos = 0;
#pragma unroll
    for (int u = 0; u < 4; ++u) {
#pragma unroll
        for (int v = 0; v < 4; ++v) {
            int ri = tr + 16 * u, rj = tc + 16 * v;
            int gi = bi * TILE + ri, gj = bj * TILE + rj;
            if (gi < gj && gj < N) {
                float s     = acc[u][v];
                float q     = floorf(__fdiv_rn(__fadd_rn(s, 1.0f), step));
                float delta = __fsub_rn(__fmul_rn(q, step), 1.0f);  // == t_q bitwise
                int   j0    = (int)q;
                bool  eq    = (clsA[ri] == clsB[rj]);
                float* h    = eq ? hist : (hist + T_BINS);
                if (eq) ++localPos;
                // falling edge: wb = (-s + t_q + step)/step into bin q (always)
                if (j0 >= 0 && j0 < T_BINS) {
                    float wb = __fdiv_rn(
                        __fadd_rn(__fadd_rn(-s, delta), step), step);
                    atomicAdd(&h[j0], wb);
                }
                // rising edge: wa into bin q+1 ONLY on bitwise edge match
                int j1 = j0 + 1;
                if (j1 >= 0 && j1 < T_BINS) {
                    float t1 = __fadd_rn(-1.0f,
                               __fmul_rn(__fadd_rn(q, 1.0f), step));
                    if (delta == __fsub_rn(t1, step)) {
                        float wa = __fdiv_rn(
                            __fadd_rn(__fsub_rn(s, t1), step), step);
                        atomicAdd(&h[j1], wa);
                    }
                }
            }
        }
    }
    if (localPos) atomicAdd(sPos, localPos);
    __syncthreads();

    float* outp = g_part[blockIdx.x];
    for (int i = tid; i < 2 * T_BINS; i += 256) outp[i] = hist[i];
    if (tid == 0) outp[2 * T_BINS] = (float)(*sPos);
}

__global__ void finalize_kernel(float* __restrict__ out, int nblocks, int N)
{
    __shared__ float hp[T_BINS], hn[T_BINS];
    int j = threadIdx.x;
    if (j < T_BINS) {
        float p = 0.f, n = 0.f;
        for (int b = 0; b < nblocks; ++b) {
            p += g_part[b][j];
            n += g_part[b][T_BINS + j];
        }
        hp[j] = p; hn[j] = n;
    }
    __syncthreads();
    if (j == 0) {
        float cnt = 0.f;
        for (int b = 0; b < nblocks; ++b) cnt += g_part[b][2 * T_BINS];
        float Ptot    = 0.5f * (float)N * (float)(N - 1);
        float posSize = cnt;
        float negSize = Ptot - cnt;
        float cdf = 0.f, loss = 0.f;
        for (int t = 0; t < T_BINS; ++t) {
            cdf  += hp[t] / posSize;                 // inclusive cumsum
            loss += (hn[t] / negSize) * cdf;
        }
        out[0] = loss;
    }
}

extern "C" void kernel_launch(void* const* d_in, const int* in_sizes, int n_in,
                              void* d_out, int out_size)
{
    const float* feats = (const float*)d_in[0];
    const int*   cls   = (const int*)d_in[1];
    int N  = in_sizes[1];                 // classes element count = number of rows
    int NT = (N + TILE - 1) / TILE;
    int nblocks = NT * (NT + 1) / 2;      // 136 for N=1024 (MAXB-bounded)
    if (nblocks > MAXB) nblocks = MAXB;   // defensive; never hit for this problem

    size_t smem = (size_t)(2 * TILE * PADW + 2 * T_BINS) * sizeof(float)
                + (size_t)(2 * TILE + 4) * sizeof(int);
    cudaFuncSetAttribute(hist_pairs_kernel,
                         cudaFuncAttributeMaxDynamicSharedMemorySize, (int)smem);

    hist_pairs_kernel<<<nblocks, 256, smem>>>(feats, cls, N, NT);
    finalize_kernel<<<1, 192>>>((float*)d_out, nblocks, N);
}

// round 4
// speedup vs baseline: 1.6845x; 1.6845x over previous
#include <cuda_runtime.h>

#define T_BINS 151
#define TILE   64
#define PADW   132          // 128 + 4 floats pad: float4-aligned, bank-offset 4/row
#define MAXB   600

// Per-block partial results: [0..150] pos hist, [151..301] neg hist, [302] pos count.
// Each block fully overwrites its own row -> no zero-init kernel needed.
__device__ float g_part[MAXB][2 * T_BINS + 4];

__global__ __launch_bounds__(256) void hist_pairs_kernel(
    const float* __restrict__ feats, const int* __restrict__ cls,
    int N, int NT)
{
    extern __shared__ float sm[];
    float* As   = sm;                         // TILE x PADW
    float* Bs   = As + TILE * PADW;           // TILE x PADW
    float* hist = Bs + TILE * PADW;           // 2 * T_BINS
    int*   clsA = (int*)(hist + 2 * T_BINS);  // TILE
    int*   clsB = clsA + TILE;                // TILE
    int*   sPos = clsB + TILE;                // 1

    const int tid = threadIdx.x;

    // Decode linear block id -> upper-triangular tile (bi, bj), bi <= bj.
    int k = blockIdx.x, bi = 0;
    while (k >= NT - bi) { k -= NT - bi; ++bi; }
    const int bj = bi + k;

    for (int i = tid; i < 2 * T_BINS; i += 256) hist[i] = 0.0f;
    if (tid == 0) *sPos = 0;
    if (tid < TILE) {
        int gi = bi * TILE + tid;
        clsA[tid] = (gi < N) ? cls[gi] : -1;
        int gj = bj * TILE + tid;
        clsB[tid] = (gj < N) ? cls[gj] : -2;
    }

    // Load both feature tiles (64 rows x 128 floats each) as float4, coalesced.
    const float4* f4 = (const float4*)feats;
    for (int idx = tid; idx < TILE * 32; idx += 256) {
        int r = idx >> 5, c = idx & 31;
        int gi = bi * TILE + r;
        float4 va = (gi < N) ? f4[gi * 32 + c] : make_float4(0.f, 0.f, 0.f, 0.f);
        *(float4*)(As + r * PADW + c * 4) = va;
        int gj = bj * TILE + r;
        float4 vb = (gj < N) ? f4[gj * 32 + c] : make_float4(0.f, 0.f, 0.f, 0.f);
        *(float4*)(Bs + r * PADW + c * 4) = vb;
    }
    __syncthreads();

    const int tr = tid >> 4;   // 0..15
    const int tc = tid & 15;   // 0..15

    // 4x4 register micro-tile: rows tr + 16u, cols tc + 16v.
    float acc[4][4];
#pragma unroll
    for (int u = 0; u < 4; ++u)
#pragma unroll
        for (int v = 0; v < 4; ++v) acc[u][v] = 0.0f;

    for (int kk = 0; kk < 128; kk += 4) {
        float4 a[4], b[4];
#pragma unroll
        for (int u = 0; u < 4; ++u)
            a[u] = *(const float4*)(As + (tr + 16 * u) * PADW + kk);
#pragma unroll
        for (int v = 0; v < 4; ++v)
            b[v] = *(const float4*)(Bs + (tc + 16 * v) * PADW + kk);
#pragma unroll
        for (int u = 0; u < 4; ++u)
#pragma unroll
            for (int v = 0; v < 4; ++v)
                acc[u][v] += a[u].x * b[v].x + a[u].y * b[v].y
                           + a[u].z * b[v].z + a[u].w * b[v].w;
    }

    // ---- Binning: bit-exact replication of the reference's fp32 semantics ----
    // Reference (all fp32, NO FMA contraction — XLA emits mul-then-add):
    //   delta = floor((s+1)/step)*step - 1
    //   indsb (bin q):    delta == -1 + q*step        -> ALWAYS true bitwise
    //   indsa (bin q+1):  delta == (-1+(q+1)*step) - step
    //                      -> different rounding path, usually FALSE; wa dropped.
    // _rn intrinsics prevent FMA contraction (contraction broke the equality).
    const float step = (float)(2.0 / 150.0);
    int localPos = 0;
#pragma unroll
    for (int u = 0; u < 4; ++u) {
#pragma unroll
        for (int v = 0; v < 4; ++v) {
            int ri = tr + 16 * u, rj = tc + 16 * v;
            int gi = bi * TILE + ri, gj = bj * TILE + rj;
            if (gi < gj && gj < N) {
                float s     = acc[u][v];
                float q     = floorf(__fdiv_rn(__fadd_rn(s, 1.0f), step));
                float delta = __fsub_rn(__fmul_rn(q, step), 1.0f);  // == t_q bitwise
                int   j0    = (int)q;
                bool  eq    = (clsA[ri] == clsB[rj]);
                float* h    = eq ? hist : (hist + T_BINS);
                if (eq) ++localPos;
                // falling edge: wb = (-s + t_q + step)/step into bin q (always)
                if (j0 >= 0 && j0 < T_BINS) {
                    float wb = __fdiv_rn(
                        __fadd_rn(__fadd_rn(-s, delta), step), step);
                    atomicAdd(&h[j0], wb);
                }
                // rising edge: wa into bin q+1 ONLY on bitwise edge match
                int j1 = j0 + 1;
                if (j1 >= 0 && j1 < T_BINS) {
                    float t1 = __fadd_rn(-1.0f,
                               __fmul_rn(__fadd_rn(q, 1.0f), step));
                    if (delta == __fsub_rn(t1, step)) {
                        float wa = __fdiv_rn(
                            __fadd_rn(__fsub_rn(s, t1), step), step);
                        atomicAdd(&h[j1], wa);
                    }
                }
            }
        }
    }
    if (localPos) atomicAdd(sPos, localPos);
    __syncthreads();

    float* outp = g_part[blockIdx.x];
    for (int i = tid; i < 2 * T_BINS; i += 256) outp[i] = hist[i];
    if (tid == 0) outp[2 * T_BINS] = (float)(*sPos);
}

// Fully parallel finalize: per-bin block reduce (302 threads), tree-reduced
// pos count, Hillis-Steele inclusive scan for the CDF, tree-reduced dot.
// Replaces 302 serial fp divides + serial loops (42.7us) with ~3us of work.
__global__ __launch_bounds__(512) void finalize_kernel(
    float* __restrict__ out, int nblocks, int N)
{
    __shared__ float hp[T_BINS], hn[T_BINS], red[512];
    __shared__ float s_inv_pos, s_inv_neg;
    const int tid = threadIdx.x;

    // pos-count partial sums (each thread strides over blocks)
    float c = 0.f;
    for (int b = tid; b < nblocks; b += 512) c += g_part[b][2 * T_BINS];
    red[tid] = c;

    // per-bin sums across blocks: thread tid owns bin tid (coalesced rows)
    float acc = 0.f;
    if (tid < 2 * T_BINS) {
#pragma unroll 4
        for (int b = 0; b < nblocks; ++b) acc += g_part[b][tid];
    }
    __syncthreads();

    // reduce pos count
#pragma unroll
    for (int s = 256; s > 0; s >>= 1) {
        if (tid < s) red[tid] += red[tid + s];
        __syncthreads();
    }
    if (tid == 0) {
        float cnt  = red[0];
        float Ptot = 0.5f * (float)N * (float)(N - 1);
        s_inv_pos = 1.0f / cnt;
        s_inv_neg = 1.0f / (Ptot - cnt);
    }
    __syncthreads();

    if (tid < T_BINS)               hp[tid]          = acc * s_inv_pos;
    else if (tid < 2 * T_BINS)      hn[tid - T_BINS] = acc * s_inv_neg;
    __syncthreads();

    // inclusive scan of hp (Hillis-Steele, 8 steps)
    for (int off = 1; off < T_BINS; off <<= 1) {
        float v = (tid < T_BINS && tid >= off) ? hp[tid - off] : 0.f;
        __syncthreads();
        if (tid < T_BINS) hp[tid] += v;
        __syncthreads();
    }

    // dot(hn, cdf) via tree reduce
    red[tid] = (tid < T_BINS) ? hn[tid] * hp[tid] : 0.f;
    __syncthreads();
#pragma unroll
    for (int s = 256; s > 0; s >>= 1) {
        if (tid < s) red[tid] += red[tid + s];
        __syncthreads();
    }
    if (tid == 0) out[0] = red[0];
}

extern "C" void kernel_launch(void* const* d_in, const int* in_sizes, int n_in,
                              void* d_out, int out_size)
{
    const float* feats = (const float*)d_in[0];
    const int*   cls   = (const int*)d_in[1];
    int N  = in_sizes[1];                 // classes element count = number of rows
    int NT = (N + TILE - 1) / TILE;
    int nblocks = NT * (NT + 1) / 2;      // 136 for N=1024 (MAXB-bounded)
    if (nblocks > MAXB) nblocks = MAXB;   // defensive; never hit for this problem

    size_t smem = (size_t)(2 * TILE * PADW + 2 * T_BINS) * sizeof(float)
                + (size_t)(2 * TILE + 4) * sizeof(int);
    cudaFuncSetAttribute(hist_pairs_kernel,
                         cudaFuncAttributeMaxDynamicSharedMemorySize, (int)smem);

    hist_pairs_kernel<<<nblocks, 256, smem>>>(feats, cls, N, NT);
    finalize_kernel<<<1, 512>>>((float*)d_out, nblocks, N);
}

// round 6
// speedup vs baseline: 2.3729x; 1.4087x over previous
#include <cuda_runtime.h>

#define T_BINS 151
#define TILE   64
#define PADW   132          // 128 + 4 floats pad: float4-aligned, bank-offset 4/row

// Global accumulators: [0..150] pos hist, [151..301] neg hist, [302] pos count.
// Zeroed by zero_kernel at the start of every replay (device globals persist).
__device__ float g_hist[2 * T_BINS + 1];

__global__ void zero_kernel()
{
    int i = threadIdx.x;
    if (i < 2 * T_BINS + 1) g_hist[i] = 0.0f;
}

__global__ __launch_bounds__(256) void hist_pairs_kernel(
    const float* __restrict__ feats, const int* __restrict__ cls,
    int N, int NT)
{
    extern __shared__ float sm[];
    float* As   = sm;                         // TILE x PADW
    float* Bs   = As + TILE * PADW;           // TILE x PADW
    float* hist = Bs + TILE * PADW;           // 2 * T_BINS
    int*   clsA = (int*)(hist + 2 * T_BINS);  // TILE
    int*   clsB = clsA + TILE;                // TILE
    int*   sPos = clsB + TILE;                // 1

    const int tid = threadIdx.x;

    // Decode linear block id -> upper-triangular tile (bi, bj), bi <= bj.
    int k = blockIdx.x, bi = 0;
    while (k >= NT - bi) { k -= NT - bi; ++bi; }
    const int bj = bi + k;

    for (int i = tid; i < 2 * T_BINS; i += 256) hist[i] = 0.0f;
    if (tid == 0) *sPos = 0;
    if (tid < TILE) {
        int gi = bi * TILE + tid;
        clsA[tid] = (gi < N) ? cls[gi] : -1;
        int gj = bj * TILE + tid;
        clsB[tid] = (gj < N) ? cls[gj] : -2;
    }

    // Load both feature tiles (64 rows x 128 floats each) as float4, coalesced.
    const float4* f4 = (const float4*)feats;
    for (int idx = tid; idx < TILE * 32; idx += 256) {
        int r = idx >> 5, c = idx & 31;
        int gi = bi * TILE + r;
        float4 va = (gi < N) ? f4[gi * 32 + c] : make_float4(0.f, 0.f, 0.f, 0.f);
        *(float4*)(As + r * PADW + c * 4) = va;
        int gj = bj * TILE + r;
        float4 vb = (gj < N) ? f4[gj * 32 + c] : make_float4(0.f, 0.f, 0.f, 0.f);
        *(float4*)(Bs + r * PADW + c * 4) = vb;
    }
    __syncthreads();

    const int tr = tid >> 4;   // 0..15
    const int tc = tid & 15;   // 0..15

    // 4x4 register micro-tile: rows tr + 16u, cols tc + 16v.
    float acc[4][4];
#pragma unroll
    for (int u = 0; u < 4; ++u)
#pragma unroll
        for (int v = 0; v < 4; ++v) acc[u][v] = 0.0f;

    for (int kk = 0; kk < 128; kk += 4) {
        float4 a[4], b[4];
#pragma unroll
        for (int u = 0; u < 4; ++u)
            a[u] = *(const float4*)(As + (tr + 16 * u) * PADW + kk);
#pragma unroll
        for (int v = 0; v < 4; ++v)
            b[v] = *(const float4*)(Bs + (tc + 16 * v) * PADW + kk);
#pragma unroll
        for (int u = 0; u < 4; ++u)
#pragma unroll
            for (int v = 0; v < 4; ++v)
                acc[u][v] += a[u].x * b[v].x + a[u].y * b[v].y
                           + a[u].z * b[v].z + a[u].w * b[v].w;
    }

    // ---- Binning: bit-exact replication of the reference's fp32 semantics ----
    // Reference (all fp32, NO FMA contraction — XLA emits mul-then-add):
    //   delta = floor((s+1)/step)*step - 1
    //   indsb (bin q):    delta == -1 + q*step        -> ALWAYS true bitwise
    //   indsa (bin q+1):  delta == (-1+(q+1)*step) - step
    //                      -> different rounding path, usually FALSE; wa dropped.
    // _rn intrinsics prevent FMA contraction (contraction broke the equality).
    const float step = (float)(2.0 / 150.0);
    int localPos = 0;
#pragma unroll
    for (int u = 0; u < 4; ++u) {
#pragma unroll
        for (int v = 0; v < 4; ++v) {
            int ri = tr + 16 * u, rj = tc + 16 * v;
            int gi = bi * TILE + ri, gj = bj * TILE + rj;
            if (gi < gj && gj < N) {
                float s     = acc[u][v];
                float q     = floorf(__fdiv_rn(__fadd_rn(s, 1.0f), step));
                float delta = __fsub_rn(__fmul_rn(q, step), 1.0f);  // == t_q bitwise
                int   j0    = (int)q;
                bool  eq    = (clsA[ri] == clsB[rj]);
                float* h    = eq ? hist : (hist + T_BINS);
                if (eq) ++localPos;
                // falling edge: wb = (-s + t_q + step)/step into bin q (always)
                if (j0 >= 0 && j0 < T_BINS) {
                    float wb = __fdiv_rn(
                        __fadd_rn(__fadd_rn(-s, delta), step), step);
                    atomicAdd(&h[j0], wb);
                }
                // rising edge: wa into bin q+1 ONLY on bitwise edge match
                int j1 = j0 + 1;
                if (j1 >= 0 && j1 < T_BINS) {
                    float t1 = __fadd_rn(-1.0f,
                               __fmul_rn(__fadd_rn(q, 1.0f), step));
                    if (delta == __fsub_rn(t1, step)) {
                        float wa = __fdiv_rn(
                            __fadd_rn(__fsub_rn(s, t1), step), step);
                        atomicAdd(&h[j1], wa);
                    }
                }
            }
        }
    }
    if (localPos) atomicAdd(sPos, localPos);
    __syncthreads();

    // Flush per-block shared histogram straight into the global accumulator.
    // 302 float atomics per block to distinct L2 addresses; ~136 blocks
    // serialize per-address on the LTS atomic ALU but hide under the wave.
    for (int i = tid; i < 2 * T_BINS; i += 256) {
        float v = hist[i];
        if (v != 0.0f) atomicAdd(&g_hist[i], v);
    }
    if (tid == 0 && *sPos) atomicAdd(&g_hist[2 * T_BINS], (float)(*sPos));
}

// Tiny finalize: 303 global loads, 2 reciprocals, 151-wide inclusive scan,
// dot product. 256 threads (POWER OF TWO — the 192-thread tree reduce in R5
// dropped red[2] ≈ 1/3 of the loss).
__global__ __launch_bounds__(256) void finalize_kernel(
    float* __restrict__ out, int N)
{
    __shared__ float hp[T_BINS], hn[T_BINS], red[256];
    __shared__ float s_inv_pos, s_inv_neg;
    const int tid = threadIdx.x;

    if (tid == 0) {
        float cnt  = g_hist[2 * T_BINS];
        float Ptot = 0.5f * (float)N * (float)(N - 1);
        s_inv_pos = 1.0f / cnt;
        s_inv_neg = 1.0f / (Ptot - cnt);
    }
    float vp = 0.f, vn = 0.f;
    if (tid < T_BINS) {
        vp = g_hist[tid];
        vn = g_hist[T_BINS + tid];
    }
    __syncthreads();
    if (tid < T_BINS) {
        hp[tid] = vp * s_inv_pos;
        hn[tid] = vn * s_inv_neg;
    }
    __syncthreads();

    // inclusive scan of hp (Hillis-Steele, 8 steps)
    for (int off = 1; off < T_BINS; off <<= 1) {
        float v = (tid < T_BINS && tid >= off) ? hp[tid - off] : 0.f;
        __syncthreads();
        if (tid < T_BINS) hp[tid] += v;
        __syncthreads();
    }

    // dot(hn, cdf) via power-of-2 tree reduce over 256 slots
    red[tid] = (tid < T_BINS) ? hn[tid] * hp[tid] : 0.f;
    __syncthreads();
#pragma unroll
    for (int s = 128; s > 0; s >>= 1) {
        if (tid < s) red[tid] += red[tid + s];
        __syncthreads();
    }
    if (tid == 0) out[0] = red[0];
}

extern "C" void kernel_launch(void* const* d_in, const int* in_sizes, int n_in,
                              void* d_out, int out_size)
{
    const float* feats = (const float*)d_in[0];
    const int*   cls   = (const int*)d_in[1];
    int N  = in_sizes[1];                 // classes element count = number of rows
    int NT = (N + TILE - 1) / TILE;
    int nblocks = NT * (NT + 1) / 2;      // 136 for N=1024

    size_t smem = (size_t)(2 * TILE * PADW + 2 * T_BINS) * sizeof(float)
                + (size_t)(2 * TILE + 4) * sizeof(int);
    cudaFuncSetAttribute(hist_pairs_kernel,
                         cudaFuncAttributeMaxDynamicSharedMemorySize, (int)smem);

    zero_kernel<<<1, 320>>>();
    hist_pairs_kernel<<<nblocks, 256, smem>>>(feats, cls, N, NT);
    finalize_kernel<<<1, 256>>>((float*)d_out, N);
}